// round 6
// baseline (speedup 1.0000x reference)
#include <cuda_runtime.h>
#include <cstdint>
#include <cstddef>

// AlarmworkRNN reduced form: only state row SEQ-1 (2047) reaches the output,
// so the scan collapses to a 256-step recurrence on two 1024-vectors.
//
// R6 = R5's proven kernel with ONE protocol change: the central atomic
// count/epoch barrier is replaced by a decentralized all-strong-atomic slot
// barrier (1 writer/slot via atomicExch, readers poll with atomicAdd(,0) +
// __threadfence). Removes two contended ATOMG round trips + leader release
// hop from every step. Data path / publish format / state loads identical
// to R5. Plus: float4 accumulators in the dot products (compute-only).

#define ND   256
#define SEQ  2048
#define NI   256
#define NH   1024
#define NO   256
#define GRID 128
#define TPB  256
#define H_PER 8
#define O_PER 2
#define TAGS 8          // slot stride in unsigned (32B sector spacing)

__device__ unsigned g_slot[GRID * TAGS];   // zero-init; monotonic across replays
// Publication k lives in buffer k&1.
__device__ float g_z1 [2][NH];
__device__ float g_z2 [2][NH];
__device__ float g_z12[2][NH];

__device__ __forceinline__ float warp_dot4(const float4* __restrict__ v,
                                           const float4* __restrict__ wgt,
                                           int n4, int lane) {
    float4 s = make_float4(0.f, 0.f, 0.f, 0.f);
    #pragma unroll 4
    for (int i = lane; i < n4; i += 32) {
        float4 a = v[i];
        float4 b = wgt[i];
        s.x = fmaf(a.x, b.x, s.x);
        s.y = fmaf(a.y, b.y, s.y);
        s.z = fmaf(a.z, b.z, s.z);
        s.w = fmaf(a.w, b.w, s.w);
    }
    return (s.x + s.y) + (s.z + s.w);
}
__device__ __forceinline__ float warp_reduce(float a) {
    #pragma unroll
    for (int off = 16; off; off >>= 1)
        a += __shfl_xor_sync(0xffffffffu, a, off);
    return a;
}

extern __shared__ float smem[];
// floats: ws_rec1[8192] ws_in1[2048] ws_rec2[8192] ws_in2[2048] ws_out[2048]
//         z12s[1024] z2s[1024] zout[1024] xs[256] b1s[8] b2s[8] bos[2]
#define OFF_REC1 0
#define OFF_IN1  8192
#define OFF_REC2 10240
#define OFF_IN2  18432
#define OFF_OUT  20480
#define OFF_Z12  22528
#define OFF_Z2   23552
#define OFF_ZO   24576
#define OFF_XS   25600
#define OFF_B1   25856
#define OFF_B2   25864
#define OFF_BO   25872
#define SMEM_FLOATS 25888

__global__ void __launch_bounds__(TPB, 1)
rnn_kernel(const float* __restrict__ x,
           const float* __restrict__ W_in1, const float* __restrict__ b_in1,
           const float* __restrict__ W_rec1,
           const float* __restrict__ W_in2, const float* __restrict__ b_in2,
           const float* __restrict__ W_rec2,
           const float* __restrict__ W_out, const float* __restrict__ b_out,
           float* __restrict__ out) {
    float* ws_rec1 = smem + OFF_REC1;
    float* ws_in1  = smem + OFF_IN1;
    float* ws_rec2 = smem + OFF_REC2;
    float* ws_in2  = smem + OFF_IN2;
    float* ws_out  = smem + OFF_OUT;
    float* z12s    = smem + OFF_Z12;
    float* z2s     = smem + OFF_Z2;
    float* zout    = smem + OFF_ZO;
    float* xs      = smem + OFF_XS;
    float* b1s     = smem + OFF_B1;
    float* b2s     = smem + OFF_B2;
    float* bos     = smem + OFF_BO;

    const int tid   = threadIdx.x;
    const int cta   = blockIdx.x;
    const int w     = tid >> 5;
    const int lane  = tid & 31;
    const int jbase = cta * H_PER;
    const int kbase = cta * O_PER;

    // Slot base: every CTA publishes exactly ND tags per launch, so all slots
    // are equal at launch entry (zero on first launch). Strong atomic read.
    const unsigned base = atomicAdd(&g_slot[cta * TAGS], 0u);

    // ---- Stage weight column slices into SMEM (R5-verbatim) ----
    for (int e = tid; e < H_PER * NH; e += TPB) {
        int jj = e >> 10, i = e & (NH - 1);
        ws_rec1[e] = W_rec1[i * NH + jbase + jj];
        ws_rec2[e] = W_rec2[i * NH + jbase + jj];
    }
    for (int e = tid; e < H_PER * NI; e += TPB) {
        int jj = e >> 8, i = e & (NI - 1);
        ws_in1[e] = W_in1[i * NH + jbase + jj];
        ws_in2[e] = W_in2[i * NH + jbase + jj];
    }
    for (int e = tid; e < O_PER * NH; e += TPB) {
        int kk = e >> 10, i = e & (NH - 1);
        ws_out[e] = W_out[i * NO + kbase + kk];
    }
    if (tid < H_PER) {
        b1s[tid] = b_in1[jbase + tid];
        b2s[tid] = b_in2[jbase + tid];
    }
    if (tid < O_PER) bos[tid] = b_out[kbase + tid];

    float z2reg = 0.f;   // warp-uniform: z2 value of column jbase+w

    // ---- Iteration 0: compute pub 1 from zero state (no barrier needed) ----
    for (int i = tid; i < NH; i += TPB) { z12s[i] = 0.f; z2s[i] = 0.f; }
    xs[tid] = x[(size_t)(SEQ - 1) * NI + tid];          // x row 0
    __syncthreads();
    {
        float a1 = warp_dot4((const float4*)xs,
                             (const float4*)(ws_in1 + w * NI), NI / 4, lane)
                 + warp_dot4((const float4*)z12s,
                             (const float4*)(ws_rec1 + w * NH), NH / 4, lane);
        a1 = warp_reduce(a1);
        float a2 = warp_dot4((const float4*)xs,
                             (const float4*)(ws_in2 + w * NI), NI / 4, lane)
                 + warp_dot4((const float4*)z2s,
                             (const float4*)(ws_rec2 + w * NH), NH / 4, lane);
        a2 = warp_reduce(a2);
        const float z1n = tanhf(a1 + b1s[w]);
        z2reg = tanhf(a2 + b2s[w]);
        if (lane == 0) {            // publish pub 1 (buffer 1), plain stores
            g_z1 [1][jbase + w] = z1n;
            g_z2 [1][jbase + w] = z2reg;
            g_z12[1][jbase + w] = z1n + z2reg;
        }
    }

    float xpref = __ldg(&x[((size_t)1 * SEQ + (SEQ - 1)) * NI + tid]);  // row 1

    // ---- Iterations 1..ND: flag pub t -> wait all -> load pub t -> compute ----
    for (int t = 1; t <= ND; t++) {
        const int cb   = t & 1;
        const int nbuf = (t + 1) & 1;
        const bool ev  = ((t & 1) == 0);
        const unsigned target = base + (unsigned)t;

        __syncthreads();                       // publish stores issued CTA-wide
        if (tid == 0) {
            __threadfence();                   // data before flag (gpu scope)
            atomicExch(&g_slot[cta * TAGS], target);   // flag: pub t published
        }
        if (tid < GRID) {
            // Wait until every CTA has flagged pub t. Strong reads; 1 slot/thread.
            while ((int)(atomicAdd(&g_slot[tid * TAGS], 0u) - target) < 0) { }
            __threadfence();                   // acquire: flag before data reads
        } else if (w >= 6 && t >= 2) {
            // out[t-2] = tanh(z1(pub t-1) . Wout + bo), in the wait window.
            float a = warp_dot4((const float4*)zout,
                                (const float4*)(ws_out + (w - 6) * NH),
                                NH / 4, lane);
            a = warp_reduce(a);
            if (lane == 0)
                out[(size_t)(t - 2) * NO + kbase + (w - 6)] =
                    tanhf(a + bos[w - 6]);
        }
        __syncthreads();   // pub t visible grid-wide

        // Load pub t (plain float4 loads, R5-verbatim).
        ((float4*)z12s)[tid] = ((const float4*)g_z12[cb])[tid];
        ((float4*)zout)[tid] = ((const float4*)g_z1 [cb])[tid];
        if (ev)
            ((float4*)z2s)[tid] = ((const float4*)g_z2[cb])[tid];
        xs[tid] = xpref;
        __syncthreads();

        if (t < ND) {
            // Prefetch x row t+1 (consumed next iteration; latency hidden).
            if (t + 1 < ND)
                xpref = __ldg(&x[((size_t)(t + 1) * SEQ + (SEQ - 1)) * NI + tid]);

            float a1 = warp_dot4((const float4*)xs,
                                 (const float4*)(ws_in1 + w * NI), NI / 4, lane)
                     + warp_dot4((const float4*)z12s,
                                 (const float4*)(ws_rec1 + w * NH), NH / 4, lane);
            a1 = warp_reduce(a1);
            float a2 = 0.f;
            if (ev) {
                a2 = warp_dot4((const float4*)xs,
                               (const float4*)(ws_in2 + w * NI), NI / 4, lane)
                   + warp_dot4((const float4*)z2s,
                               (const float4*)(ws_rec2 + w * NH), NH / 4, lane);
                a2 = warp_reduce(a2);
            }
            const float z1n = tanhf(a1 + b1s[w]);
            if (ev) z2reg = tanhf(a2 + b2s[w]);
            if (lane == 0) {       // publish pub t+1 (plain stores)
                g_z1 [nbuf][jbase + w] = z1n;
                g_z2 [nbuf][jbase + w] = z2reg;   // odd t: republish held z2
                g_z12[nbuf][jbase + w] = z1n + z2reg;
            }
        }
    }

    // ---- Tail: out[ND-1] from pub ND (zout stashed at iter ND) ----
    if (w >= 6) {
        float a = warp_dot4((const float4*)zout,
                            (const float4*)(ws_out + (w - 6) * NH), NH / 4, lane);
        a = warp_reduce(a);
        if (lane == 0)
            out[(size_t)(ND - 1) * NO + kbase + (w - 6)] = tanhf(a + bos[w - 6]);
    }
}

extern "C" void kernel_launch(void* const* d_in, const int* in_sizes, int n_in,
                              void* d_out, int out_size) {
    const float* x      = (const float*)d_in[0];
    const float* W_in1  = (const float*)d_in[1];
    const float* b_in1  = (const float*)d_in[2];
    const float* W_rec1 = (const float*)d_in[3];
    const float* W_in2  = (const float*)d_in[4];
    const float* b_in2  = (const float*)d_in[5];
    const float* W_rec2 = (const float*)d_in[6];
    const float* W_out  = (const float*)d_in[7];
    const float* b_out  = (const float*)d_in[8];
    float* out = (float*)d_out;

    const size_t shmem = SMEM_FLOATS * sizeof(float);
    cudaFuncSetAttribute(rnn_kernel, cudaFuncAttributeMaxDynamicSharedMemorySize,
                         (int)shmem);
    rnn_kernel<<<GRID, TPB, shmem>>>(x, W_in1, b_in1, W_rec1,
                                     W_in2, b_in2, W_rec2, W_out, b_out, out);
}

// round 7
// speedup vs baseline: 1.3704x; 1.3704x over previous
#include <cuda_runtime.h>
#include <cstdint>
#include <cstddef>

// AlarmworkRNN reduced form: only state row SEQ-1 (2047) reaches the output,
// so the scan collapses to a 256-step recurrence on two 1024-vectors.
//
// R7 = R6 with ONE change: flag polling uses volatile loads (normal L2 read
// path, concurrent) instead of atomicAdd(,0) (LTS atomic-ALU serialized --
// the R6 regression). Flag WRITE stays atomicExch to per-CTA slots (proven,
// contention-free); consumer keeps the __threadfence acquire after detection
// (the piece whose absence sank R3/R4). Data path identical to R5/R6.

#define ND   256
#define SEQ  2048
#define NI   256
#define NH   1024
#define NO   256
#define GRID 128
#define TPB  256
#define H_PER 8
#define O_PER 2
#define TAGS 8          // slot stride in unsigned (32B sector spacing)

__device__ unsigned g_slot[GRID * TAGS];   // zero-init; monotonic across replays
// Publication k lives in buffer k&1.
__device__ float g_z1 [2][NH];
__device__ float g_z2 [2][NH];
__device__ float g_z12[2][NH];

__device__ __forceinline__ float warp_dot4(const float4* __restrict__ v,
                                           const float4* __restrict__ wgt,
                                           int n4, int lane) {
    float4 s = make_float4(0.f, 0.f, 0.f, 0.f);
    #pragma unroll 4
    for (int i = lane; i < n4; i += 32) {
        float4 a = v[i];
        float4 b = wgt[i];
        s.x = fmaf(a.x, b.x, s.x);
        s.y = fmaf(a.y, b.y, s.y);
        s.z = fmaf(a.z, b.z, s.z);
        s.w = fmaf(a.w, b.w, s.w);
    }
    return (s.x + s.y) + (s.z + s.w);
}
__device__ __forceinline__ float warp_reduce(float a) {
    #pragma unroll
    for (int off = 16; off; off >>= 1)
        a += __shfl_xor_sync(0xffffffffu, a, off);
    return a;
}

extern __shared__ float smem[];
// floats: ws_rec1[8192] ws_in1[2048] ws_rec2[8192] ws_in2[2048] ws_out[2048]
//         z12s[1024] z2s[1024] zout[1024] xs[256] b1s[8] b2s[8] bos[2]
#define OFF_REC1 0
#define OFF_IN1  8192
#define OFF_REC2 10240
#define OFF_IN2  18432
#define OFF_OUT  20480
#define OFF_Z12  22528
#define OFF_Z2   23552
#define OFF_ZO   24576
#define OFF_XS   25600
#define OFF_B1   25856
#define OFF_B2   25864
#define OFF_BO   25872
#define SMEM_FLOATS 25888

__global__ void __launch_bounds__(TPB, 1)
rnn_kernel(const float* __restrict__ x,
           const float* __restrict__ W_in1, const float* __restrict__ b_in1,
           const float* __restrict__ W_rec1,
           const float* __restrict__ W_in2, const float* __restrict__ b_in2,
           const float* __restrict__ W_rec2,
           const float* __restrict__ W_out, const float* __restrict__ b_out,
           float* __restrict__ out) {
    float* ws_rec1 = smem + OFF_REC1;
    float* ws_in1  = smem + OFF_IN1;
    float* ws_rec2 = smem + OFF_REC2;
    float* ws_in2  = smem + OFF_IN2;
    float* ws_out  = smem + OFF_OUT;
    float* z12s    = smem + OFF_Z12;
    float* z2s     = smem + OFF_Z2;
    float* zout    = smem + OFF_ZO;
    float* xs      = smem + OFF_XS;
    float* b1s     = smem + OFF_B1;
    float* b2s     = smem + OFF_B2;
    float* bos     = smem + OFF_BO;

    const int tid   = threadIdx.x;
    const int cta   = blockIdx.x;
    const int w     = tid >> 5;
    const int lane  = tid & 31;
    const int jbase = cta * H_PER;
    const int kbase = cta * O_PER;

    // Slot base: every CTA publishes exactly ND tags per launch, so all slots
    // are equal at launch entry (zero on first launch). Strong atomic read.
    const unsigned base = atomicAdd(&g_slot[cta * TAGS], 0u);

    // ---- Stage weight column slices into SMEM (R5-verbatim) ----
    for (int e = tid; e < H_PER * NH; e += TPB) {
        int jj = e >> 10, i = e & (NH - 1);
        ws_rec1[e] = W_rec1[i * NH + jbase + jj];
        ws_rec2[e] = W_rec2[i * NH + jbase + jj];
    }
    for (int e = tid; e < H_PER * NI; e += TPB) {
        int jj = e >> 8, i = e & (NI - 1);
        ws_in1[e] = W_in1[i * NH + jbase + jj];
        ws_in2[e] = W_in2[i * NH + jbase + jj];
    }
    for (int e = tid; e < O_PER * NH; e += TPB) {
        int kk = e >> 10, i = e & (NH - 1);
        ws_out[e] = W_out[i * NO + kbase + kk];
    }
    if (tid < H_PER) {
        b1s[tid] = b_in1[jbase + tid];
        b2s[tid] = b_in2[jbase + tid];
    }
    if (tid < O_PER) bos[tid] = b_out[kbase + tid];

    float z2reg = 0.f;   // warp-uniform: z2 value of column jbase+w

    // ---- Iteration 0: compute pub 1 from zero state (no barrier needed) ----
    for (int i = tid; i < NH; i += TPB) { z12s[i] = 0.f; z2s[i] = 0.f; }
    xs[tid] = x[(size_t)(SEQ - 1) * NI + tid];          // x row 0
    __syncthreads();
    {
        float a1 = warp_dot4((const float4*)xs,
                             (const float4*)(ws_in1 + w * NI), NI / 4, lane)
                 + warp_dot4((const float4*)z12s,
                             (const float4*)(ws_rec1 + w * NH), NH / 4, lane);
        a1 = warp_reduce(a1);
        float a2 = warp_dot4((const float4*)xs,
                             (const float4*)(ws_in2 + w * NI), NI / 4, lane)
                 + warp_dot4((const float4*)z2s,
                             (const float4*)(ws_rec2 + w * NH), NH / 4, lane);
        a2 = warp_reduce(a2);
        const float z1n = tanhf(a1 + b1s[w]);
        z2reg = tanhf(a2 + b2s[w]);
        if (lane == 0) {            // publish pub 1 (buffer 1), plain stores
            g_z1 [1][jbase + w] = z1n;
            g_z2 [1][jbase + w] = z2reg;
            g_z12[1][jbase + w] = z1n + z2reg;
        }
    }

    float xpref = __ldg(&x[((size_t)1 * SEQ + (SEQ - 1)) * NI + tid]);  // row 1

    // ---- Iterations 1..ND: flag pub t -> wait all -> load pub t -> compute ----
    for (int t = 1; t <= ND; t++) {
        const int cb   = t & 1;
        const int nbuf = (t + 1) & 1;
        const bool ev  = ((t & 1) == 0);
        const unsigned target = base + (unsigned)t;

        __syncthreads();                       // publish stores issued CTA-wide
        if (tid == 0) {
            __threadfence();                   // data before flag (gpu scope)
            atomicExch(&g_slot[cta * TAGS], target);   // flag: pub t published
        }
        if (tid < GRID) {
            // Wait until every CTA has flagged pub t.
            // Volatile loads: normal L2 read path, no atomic-ALU serialization.
            volatile unsigned* sp = &g_slot[tid * TAGS];
            while ((int)(*sp - target) < 0) { }
            __threadfence();                   // acquire: flag before data reads
        } else if (w >= 6 && t >= 2) {
            // out[t-2] = tanh(z1(pub t-1) . Wout + bo), in the wait window.
            float a = warp_dot4((const float4*)zout,
                                (const float4*)(ws_out + (w - 6) * NH),
                                NH / 4, lane);
            a = warp_reduce(a);
            if (lane == 0)
                out[(size_t)(t - 2) * NO + kbase + (w - 6)] =
                    tanhf(a + bos[w - 6]);
        }
        __syncthreads();   // pub t visible grid-wide

        // Load pub t (plain float4 loads, R5-verbatim).
        ((float4*)z12s)[tid] = ((const float4*)g_z12[cb])[tid];
        ((float4*)zout)[tid] = ((const float4*)g_z1 [cb])[tid];
        if (ev)
            ((float4*)z2s)[tid] = ((const float4*)g_z2[cb])[tid];
        xs[tid] = xpref;
        __syncthreads();

        if (t < ND) {
            // Prefetch x row t+1 (consumed next iteration; latency hidden).
            if (t + 1 < ND)
                xpref = __ldg(&x[((size_t)(t + 1) * SEQ + (SEQ - 1)) * NI + tid]);

            float a1 = warp_dot4((const float4*)xs,
                                 (const float4*)(ws_in1 + w * NI), NI / 4, lane)
                     + warp_dot4((const float4*)z12s,
                                 (const float4*)(ws_rec1 + w * NH), NH / 4, lane);
            a1 = warp_reduce(a1);
            float a2 = 0.f;
            if (ev) {
                a2 = warp_dot4((const float4*)xs,
                               (const float4*)(ws_in2 + w * NI), NI / 4, lane)
                   + warp_dot4((const float4*)z2s,
                               (const float4*)(ws_rec2 + w * NH), NH / 4, lane);
                a2 = warp_reduce(a2);
            }
            const float z1n = tanhf(a1 + b1s[w]);
            if (ev) z2reg = tanhf(a2 + b2s[w]);
            if (lane == 0) {       // publish pub t+1 (plain stores)
                g_z1 [nbuf][jbase + w] = z1n;
                g_z2 [nbuf][jbase + w] = z2reg;   // odd t: republish held z2
                g_z12[nbuf][jbase + w] = z1n + z2reg;
            }
        }
    }

    // ---- Tail: out[ND-1] from pub ND (zout stashed at iter ND) ----
    if (w >= 6) {
        float a = warp_dot4((const float4*)zout,
                            (const float4*)(ws_out + (w - 6) * NH), NH / 4, lane);
        a = warp_reduce(a);
        if (lane == 0)
            out[(size_t)(ND - 1) * NO + kbase + (w - 6)] = tanhf(a + bos[w - 6]);
    }
}

extern "C" void kernel_launch(void* const* d_in, const int* in_sizes, int n_in,
                              void* d_out, int out_size) {
    const float* x      = (const float*)d_in[0];
    const float* W_in1  = (const float*)d_in[1];
    const float* b_in1  = (const float*)d_in[2];
    const float* W_rec1 = (const float*)d_in[3];
    const float* W_in2  = (const float*)d_in[4];
    const float* b_in2  = (const float*)d_in[5];
    const float* W_rec2 = (const float*)d_in[6];
    const float* W_out  = (const float*)d_in[7];
    const float* b_out  = (const float*)d_in[8];
    float* out = (float*)d_out;

    const size_t shmem = SMEM_FLOATS * sizeof(float);
    cudaFuncSetAttribute(rnn_kernel, cudaFuncAttributeMaxDynamicSharedMemorySize,
                         (int)shmem);
    rnn_kernel<<<GRID, TPB, shmem>>>(x, W_in1, b_in1, W_rec1,
                                     W_in2, b_in2, W_rec2, W_out, b_out, out);
}

// round 8
// speedup vs baseline: 1.5228x; 1.1112x over previous
#include <cuda_runtime.h>
#include <cstdint>
#include <cstddef>

// AlarmworkRNN reduced form: only state row SEQ-1 (2047) reaches the output,
// so the scan collapses to a 256-step recurrence on two 1024-vectors.
//
// R8 = R7 (proven sync: syncthreads -> tid0 fence -> atomicExch own slot;
// volatile poll -> acquire fence) with ONE change: weights live in REGISTERS
// (warp w owns column jbase+w of both layers; warps 6-7 also own one W_out
// column), staged once via a padded SMEM transpose. Removes ~80-150KB/step of
// SMEM crossbar traffic from the critical chain. Publish format, state loads,
// barrier: byte-identical to R7.

#define ND   256
#define SEQ  2048
#define NI   256
#define NH   1024
#define NO   256
#define GRID 128
#define TPB  256
#define H_PER 8
#define O_PER 2
#define TAGS 8          // slot stride in unsigned (32B sector spacing)
#define PAD  9          // staging transpose pad (9 coprime 32 -> conflict-free)

__device__ unsigned g_slot[GRID * TAGS];   // zero-init; monotonic across replays
// Publication k lives in buffer k&1.
__device__ float g_z1 [2][NH];
__device__ float g_z2 [2][NH];
__device__ float g_z12[2][NH];

__device__ __forceinline__ float warp_reduce(float a) {
    #pragma unroll
    for (int off = 16; off; off >>= 1)
        a += __shfl_xor_sync(0xffffffffu, a, off);
    return a;
}

extern __shared__ float smem[];
// floats: stg[1024*9=9216] z12s[1024] z2s[1024] zout[1024] xs[256]
#define OFF_STG  0
#define OFF_Z12  9216
#define OFF_Z2   10240
#define OFF_ZO   11264
#define OFF_XS   12288
#define SMEM_FLOATS 12544

__global__ void __launch_bounds__(TPB, 1)
rnn_kernel(const float* __restrict__ x,
           const float* __restrict__ W_in1, const float* __restrict__ b_in1,
           const float* __restrict__ W_rec1,
           const float* __restrict__ W_in2, const float* __restrict__ b_in2,
           const float* __restrict__ W_rec2,
           const float* __restrict__ W_out, const float* __restrict__ b_out,
           float* __restrict__ out) {
    float* stg  = smem + OFF_STG;
    float* z12s = smem + OFF_Z12;
    float* z2s  = smem + OFF_Z2;
    float* zout = smem + OFF_ZO;
    float* xs   = smem + OFF_XS;

    const int tid   = threadIdx.x;
    const int cta   = blockIdx.x;
    const int w     = tid >> 5;
    const int lane  = tid & 31;
    const int jbase = cta * H_PER;
    const int kbase = cta * O_PER;

    // Slot base (uniform across CTAs: each publishes exactly ND tags/launch).
    const unsigned base = atomicAdd(&g_slot[cta * TAGS], 0u);

    // ---- Stage weights into REGISTERS via padded SMEM transpose ----
    // stg[r*PAD + c] = W[r][jbase+c]; warp w reads column w at rows lane+32i.
    float wrec1[32], wrec2[32], win1[8], win2[8], wout[32];

    for (int r = tid >> 3; r < NH; r += 32)                 // W_rec1
        stg[r * PAD + (tid & 7)] = W_rec1[r * NH + jbase + (tid & 7)];
    __syncthreads();
    #pragma unroll
    for (int i = 0; i < 32; i++)
        wrec1[i] = stg[(lane + 32 * i) * PAD + w];
    __syncthreads();

    for (int r = tid >> 3; r < NH; r += 32)                 // W_rec2
        stg[r * PAD + (tid & 7)] = W_rec2[r * NH + jbase + (tid & 7)];
    __syncthreads();
    #pragma unroll
    for (int i = 0; i < 32; i++)
        wrec2[i] = stg[(lane + 32 * i) * PAD + w];
    __syncthreads();

    for (int r = tid >> 3; r < NI; r += 32)                 // W_in1
        stg[r * PAD + (tid & 7)] = W_in1[r * NH + jbase + (tid & 7)];
    __syncthreads();
    #pragma unroll
    for (int i = 0; i < 8; i++)
        win1[i] = stg[(lane + 32 * i) * PAD + w];
    __syncthreads();

    for (int r = tid >> 3; r < NI; r += 32)                 // W_in2
        stg[r * PAD + (tid & 7)] = W_in2[r * NH + jbase + (tid & 7)];
    __syncthreads();
    #pragma unroll
    for (int i = 0; i < 8; i++)
        win2[i] = stg[(lane + 32 * i) * PAD + w];
    __syncthreads();

    for (int r = tid >> 1; r < NH; r += 128)                // W_out (2 cols)
        stg[r * PAD + (tid & 1)] = W_out[r * NO + kbase + (tid & 1)];
    __syncthreads();
    if (w >= 6) {
        #pragma unroll
        for (int i = 0; i < 32; i++)
            wout[i] = stg[(lane + 32 * i) * PAD + (w - 6)];
    }

    const float b1 = b_in1[jbase + w];
    const float b2 = b_in2[jbase + w];
    const float bo = (w >= 6) ? b_out[kbase + (w - 6)] : 0.f;

    float z2reg = 0.f;   // warp-uniform: z2 value of column jbase+w

    // ---- Iteration 0: compute pub 1 from zero state (no barrier needed) ----
    for (int i = tid; i < NH; i += TPB) { z12s[i] = 0.f; z2s[i] = 0.f; }
    xs[tid] = x[(size_t)(SEQ - 1) * NI + tid];          // x row 0
    __syncthreads();
    {
        float a1 = 0.f, a2 = 0.f;
        #pragma unroll
        for (int i = 0; i < 8; i++) {
            const float xv = xs[lane + 32 * i];
            a1 = fmaf(win1[i], xv, a1);
            a2 = fmaf(win2[i], xv, a2);
        }
        #pragma unroll
        for (int i = 0; i < 32; i++) {
            a1 = fmaf(wrec1[i], z12s[lane + 32 * i], a1);
            a2 = fmaf(wrec2[i], z2s [lane + 32 * i], a2);
        }
        a1 = warp_reduce(a1);
        a2 = warp_reduce(a2);
        const float z1n = tanhf(a1 + b1);
        z2reg = tanhf(a2 + b2);
        if (lane == 0) {            // publish pub 1 (buffer 1), plain stores
            g_z1 [1][jbase + w] = z1n;
            g_z2 [1][jbase + w] = z2reg;
            g_z12[1][jbase + w] = z1n + z2reg;
        }
    }

    float xpref = __ldg(&x[((size_t)1 * SEQ + (SEQ - 1)) * NI + tid]);  // row 1

    // ---- Iterations 1..ND: flag pub t -> wait all -> load pub t -> compute ----
    for (int t = 1; t <= ND; t++) {
        const int cb   = t & 1;
        const int nbuf = (t + 1) & 1;
        const bool ev  = ((t & 1) == 0);
        const unsigned target = base + (unsigned)t;

        __syncthreads();                       // publish stores issued CTA-wide
        if (tid == 0) {
            __threadfence();                   // data before flag (gpu scope)
            atomicExch(&g_slot[cta * TAGS], target);   // flag: pub t published
        }
        if (tid < GRID) {
            // Volatile loads: normal L2 read path, no atomic-ALU serialization.
            volatile unsigned* sp = &g_slot[tid * TAGS];
            while ((int)(*sp - target) < 0) { }
            __threadfence();                   // acquire: flag before data reads
        } else if (w >= 6 && t >= 2) {
            // out[t-2] = tanh(z1(pub t-1) . Wout + bo), in the wait window.
            float a = 0.f;
            #pragma unroll
            for (int i = 0; i < 32; i++)
                a = fmaf(wout[i], zout[lane + 32 * i], a);
            a = warp_reduce(a);
            if (lane == 0)
                out[(size_t)(t - 2) * NO + kbase + (w - 6)] = tanhf(a + bo);
        }
        __syncthreads();   // pub t visible grid-wide

        // Load pub t (plain float4 loads, R7-verbatim).
        ((float4*)z12s)[tid] = ((const float4*)g_z12[cb])[tid];
        ((float4*)zout)[tid] = ((const float4*)g_z1 [cb])[tid];
        if (ev)
            ((float4*)z2s)[tid] = ((const float4*)g_z2[cb])[tid];
        xs[tid] = xpref;
        __syncthreads();

        if (t < ND) {
            // Prefetch x row t+1 (consumed next iteration; latency hidden).
            if (t + 1 < ND)
                xpref = __ldg(&x[((size_t)(t + 1) * SEQ + (SEQ - 1)) * NI + tid]);

            float a1 = 0.f, a2 = 0.f;
            #pragma unroll
            for (int i = 0; i < 8; i++) {
                const float xv = xs[lane + 32 * i];
                a1 = fmaf(win1[i], xv, a1);
                if (ev) a2 = fmaf(win2[i], xv, a2);
            }
            #pragma unroll
            for (int i = 0; i < 32; i++) {
                a1 = fmaf(wrec1[i], z12s[lane + 32 * i], a1);
                if (ev) a2 = fmaf(wrec2[i], z2s[lane + 32 * i], a2);
            }
            a1 = warp_reduce(a1);
            if (ev) a2 = warp_reduce(a2);

            const float z1n = tanhf(a1 + b1);
            if (ev) z2reg = tanhf(a2 + b2);
            if (lane == 0) {       // publish pub t+1 (plain stores, R7-verbatim)
                g_z1 [nbuf][jbase + w] = z1n;
                g_z2 [nbuf][jbase + w] = z2reg;   // odd t: republish held z2
                g_z12[nbuf][jbase + w] = z1n + z2reg;
            }
        }
    }

    // ---- Tail: out[ND-1] from pub ND (zout stashed at iter ND) ----
    if (w >= 6) {
        float a = 0.f;
        #pragma unroll
        for (int i = 0; i < 32; i++)
            a = fmaf(wout[i], zout[lane + 32 * i], a);
        a = warp_reduce(a);
        if (lane == 0)
            out[(size_t)(ND - 1) * NO + kbase + (w - 6)] = tanhf(a + bo);
    }
}

extern "C" void kernel_launch(void* const* d_in, const int* in_sizes, int n_in,
                              void* d_out, int out_size) {
    const float* x      = (const float*)d_in[0];
    const float* W_in1  = (const float*)d_in[1];
    const float* b_in1  = (const float*)d_in[2];
    const float* W_rec1 = (const float*)d_in[3];
    const float* W_in2  = (const float*)d_in[4];
    const float* b_in2  = (const float*)d_in[5];
    const float* W_rec2 = (const float*)d_in[6];
    const float* W_out  = (const float*)d_in[7];
    const float* b_out  = (const float*)d_in[8];
    float* out = (float*)d_out;

    const size_t shmem = SMEM_FLOATS * sizeof(float);
    cudaFuncSetAttribute(rnn_kernel, cudaFuncAttributeMaxDynamicSharedMemorySize,
                         (int)shmem);
    rnn_kernel<<<GRID, TPB, shmem>>>(x, W_in1, b_in1, W_rec1,
                                     W_in2, b_in2, W_rec2, W_out, b_out, out);
}